// round 15
// baseline (speedup 1.0000x reference)
#include <cuda_runtime.h>
#include <cuda_fp16.h>
#include <cstdint>
#include <cstddef>

// Problem constants
#define kT 512
#define kB 64
#define kH 1024
#define kG 3072
#define kL 4

// Wavefront config: 128 CTAs = 4 layers x 32 slices (32 hidden units each).
// 8 warps = 4 K-groups (K=512 each of K=2048) x 2 M-halves (48 gate rows).
#define WNCTA 128
#define WTH 256
#define NSTEP (kT + kL - 1)          /* 515 */
#define RED_LD 66
#define RED_ROWS 128                  /* r(32) z(32) n_ih(32) n_hh(32) */
#define WV_SMEM ((2 * RED_ROWS * RED_LD + 192) * 4)   /* 68352 B */

// Packed weights: [cta][kg][mh][m(3)][kbl(32)][lane(32)] x uint4 (fp16 frags)
#define WP_U32 ((size_t)WNCTA * 4 * 2 * 3 * 32 * 32 * 4)   /* 12.58M u32 = 50MB */

// ---------------------------------------------------------------------------
// Scratch
// ---------------------------------------------------------------------------
__device__ unsigned g_wp_u32[WP_U32];
__device__ unsigned g_x16[(size_t)kT * 32768];   // packed fp16 x, per t: 32768 u32
__device__ unsigned g_hp16[2 * kL * 32768];      // h ping-pong per (parity, layer)
__device__ unsigned g_h016[kL * 32768];          // packed fp16 h0 per layer
__device__ unsigned g_count;
__device__ unsigned g_release;

__global__ void reset_bar_kernel() { g_count = 0u; g_release = 0u; }

// Proven threadfence grid barrier (128 CTAs). The __threadfence also emits
// CCTL.IVALL (L1D invalidate), which is what makes per-step L1 caching of h
// safe: only within-step reuse is ever served from L1.
__device__ __forceinline__ void grid_barrier(unsigned idx) {
  __syncthreads();
  if (threadIdx.x == 0) {
    __threadfence();
    unsigned old = atomicAdd(&g_count, 1u);
    if (old == (unsigned)WNCTA * (idx + 1u) - 1u) {
      __threadfence();
      asm volatile("st.release.gpu.global.u32 [%0], %1;"
                   :: "l"(&g_release), "r"(idx + 1u) : "memory");
    } else {
      while (*(volatile unsigned*)&g_release < idx + 1u) { }
    }
    __threadfence();
  }
  __syncthreads();
}

__device__ __forceinline__ float sigmoidf_(float x) {
  return 1.0f / (1.0f + expf(-x));
}

// ---------------------------------------------------------------------------
// Packed h/x layout (vectorizable): uint2 fragment units ordered
// [kb][g4 = b&7][l4 = (j>>1)&3][nt = b>>3], where the uint2 holds the
// m16n8k16 B fragment (b0 = halves k0,k0+1; b1 = halves k0+8,k0+9) with
// k0 = kb*16 + l4*2. Lane (g4,l4) reads its 8 nt fragments as 4 LDG.128.
// ---------------------------------------------------------------------------
__device__ __forceinline__ int hp_u32_index(int j, int b) {   // even j: pair (j, j+1)
  int kb = j >> 4;
  int U = ((kb * 8 + (b & 7)) * 4 + ((j >> 1) & 3)) * 8 + (b >> 3);
  return U * 2 + ((j >> 3) & 1);
}
__device__ __forceinline__ int hp_half_index(int j, int b) {  // arbitrary j
  int kb = j >> 4;
  int U = ((kb * 8 + (b & 7)) * 4 + ((j >> 1) & 3)) * 8 + (b >> 3);
  return U * 4 + ((j >> 3) & 1) * 2 + (j & 1);
}

#define MMA_F16(d, a, b0, b1)                                               \
  asm volatile(                                                             \
      "mma.sync.aligned.m16n8k16.row.col.f32.f16.f16.f32 "                  \
      "{%0,%1,%2,%3}, {%4,%5,%6,%7}, {%8,%9}, {%0,%1,%2,%3};"               \
      : "+f"(d[0]), "+f"(d[1]), "+f"(d[2]), "+f"(d[3])                      \
      : "r"(a.x), "r"(a.y), "r"(a.z), "r"(a.w), "r"(b0), "r"(b1))

// ---------------------------------------------------------------------------
// Packing kernels (idempotent, run every launch)
// ---------------------------------------------------------------------------
__global__ void pack_w_kernel(const float* __restrict__ wih,
                              const float* __restrict__ whh) {
  size_t i = (size_t)blockIdx.x * blockDim.x + threadIdx.x;
  if (i >= WP_U32) return;
  int e = (int)(i & 3);
  int lane = (int)((i >> 2) & 31);
  int kbl = (int)((i >> 7) & 31);
  int rem = (int)(i >> 12);
  int m = rem % 3; rem /= 3;
  int mh = rem & 1;
  int kg = (rem >> 1) & 3;
  int cta = rem >> 3;
  int layer = cta >> 5, slice = cta & 31;
  int mtp = mh * 3 + m;
  int gate = mtp >> 1;
  int rr = ((mtp & 1) << 4) + (lane >> 2) + ((e & 1) << 3);
  int k = (kg * 32 + kbl) * 16 + ((lane & 3) << 1) + ((e >> 1) << 3);
  int row = gate * kH + slice * 32 + rr;
  const float* W = (k < kH) ? (wih + (size_t)layer * kG * kH)
                            : (whh + (size_t)layer * kG * kH);
  int kk = k & (kH - 1);
  __half2 h2 = __floats2half2_rn(W[(size_t)row * kH + kk],
                                 W[(size_t)row * kH + kk + 1]);
  g_wp_u32[i] = *(unsigned*)&h2;
}

__global__ void pack_x_kernel(const float* __restrict__ x) {
  size_t i = (size_t)blockIdx.x * blockDim.x + threadIdx.x;  // < kT*kB*512
  int t = (int)(i >> 15);
  int r = (int)(i & 32767);
  int b = r >> 9;
  int j = (r & 511) << 1;
  const float* src = x + (size_t)t * kB * kH + (size_t)b * kH + j;
  __half2 h2 = __floats2half2_rn(src[0], src[1]);
  g_x16[(size_t)t * 32768 + hp_u32_index(j, b)] = *(unsigned*)&h2;
}

__global__ void pack_h0_kernel(const float* __restrict__ h0) {
  int i = blockIdx.x * blockDim.x + threadIdx.x;   // < kL*32768
  int layer = i >> 15;
  int r = i & 32767;
  int b = r >> 9;
  int j = (r & 511) << 1;
  const float* src = h0 + (size_t)layer * kB * kH + (size_t)b * kH + j;
  __half2 h2 = __floats2half2_rn(src[0], src[1]);
  g_h016[layer * 32768 + hp_u32_index(j, b)] = *(unsigned*)&h2;
}

// ---------------------------------------------------------------------------
// Wavefront kernel: 128 CTAs, 515 steps. Weights streamed L2-only (__ldcg,
// read-once so L1 fill is pure pollution); h/x read via L1 so the mh-twin
// warp's identical fragment loads hit L1 (halving h L2 traffic).
// ---------------------------------------------------------------------------
__global__ void __launch_bounds__(WTH, 1) wave_kernel(
    const float* __restrict__ h0f,
    const float* __restrict__ bih,
    const float* __restrict__ bhh,
    float* __restrict__ out) {
  extern __shared__ float sm[];
  float* red0 = sm;                          // [128][RED_LD]
  float* red1 = sm + RED_ROWS * RED_LD;
  float* sbias = sm + 2 * RED_ROWS * RED_LD; // [6][32]
  const int tid = threadIdx.x;
  const int lane = tid & 31;
  const int wid = tid >> 5;
  const int layer = blockIdx.x >> 5;
  const int slice = blockIdx.x & 31;
  const int j0 = slice * 32;

  // Stage biases: [bi_r, bi_z, bi_n, bh_r, bh_z, bh_n][jj]
  for (int i = tid; i < 192; i += WTH) {
    int g = i >> 5, jj = i & 31;
    sbias[i] = ((g < 3) ? bih : bhh)[(size_t)layer * kG + (g % 3) * kH + j0 + jj];
  }

  // Register-resident h_prev: thread owns 8 (jj, b) outputs.
  float hp[8];
#pragma unroll
  for (int k = 0; k < 8; k++) {
    int e = tid + k * WTH;
    int jj = e >> 6, b = e & 63;
    hp[k] = h0f[(size_t)layer * kB * kH + (size_t)b * kH + j0 + jj];
  }
  __syncthreads();

  const int kg = wid >> 1;          // K group: 0,1 = ih half; 2,3 = hh half
  const int mh = wid & 1;           // M half (3 of 6 m-tiles)
  const int g4 = lane >> 2;
  const int l4 = lane & 3;
  const uint4* wpw = (const uint4*)g_wp_u32 +
      ((((size_t)blockIdx.x * 4 + kg) * 2 + mh) * 3 * 32 * 32);

  for (int s = 0; s < NSTEP; s++) {
    int t = s - layer;
    if (t >= 0 && t < kT) {
      // B-operand source for this warp's K half
      const uint4* bsrc;
      if (kg < 2) {
        bsrc = (layer == 0)
            ? (const uint4*)(g_x16 + (size_t)t * 32768)
            : (const uint4*)(g_hp16 + (size_t)(((s - 1) & 1) * kL + (layer - 1)) * 32768);
      } else {
        bsrc = (t == 0)
            ? (const uint4*)(g_h016 + (size_t)layer * 32768)
            : (const uint4*)(g_hp16 + (size_t)(((s - 1) & 1) * kL + layer) * 32768);
      }

      float acc[3][8][4];
#pragma unroll
      for (int m = 0; m < 3; m++)
#pragma unroll
        for (int nt = 0; nt < 8; nt++)
#pragma unroll
          for (int e = 0; e < 4; e++) acc[m][nt][e] = 0.0f;

#pragma unroll 4
      for (int kbl = 0; kbl < 32; kbl++) {
        int kb_src = (kg * 32 + kbl) & 63;
        // Weights: L2-only (read-once; keep L1 for h)
        uint4 a0 = __ldcg(&wpw[(0 * 32 + kbl) * 32 + lane]);
        uint4 a1 = __ldcg(&wpw[(1 * 32 + kbl) * 32 + lane]);
        uint4 a2 = __ldcg(&wpw[(2 * 32 + kbl) * 32 + lane]);
        // h: 4 coalesced LDG.128 per lane, L1-cached (twin-warp reuse)
        int hbase = ((kb_src * 8 + g4) * 4 + l4) * 4;
        uint4 q0 = bsrc[hbase + 0];
        uint4 q1 = bsrc[hbase + 1];
        uint4 q2 = bsrc[hbase + 2];
        uint4 q3 = bsrc[hbase + 3];
        uint32_t bx[8], by[8];
        bx[0] = q0.x; by[0] = q0.y;  bx[1] = q0.z; by[1] = q0.w;
        bx[2] = q1.x; by[2] = q1.y;  bx[3] = q1.z; by[3] = q1.w;
        bx[4] = q2.x; by[4] = q2.y;  bx[5] = q2.z; by[5] = q2.w;
        bx[6] = q3.x; by[6] = q3.y;  bx[7] = q3.z; by[7] = q3.w;
#pragma unroll
        for (int nt = 0; nt < 8; nt++) {
          MMA_F16(acc[0][nt], a0, bx[nt], by[nt]);
          MMA_F16(acc[1][nt], a1, bx[nt], by[nt]);
          MMA_F16(acc[2][nt], a2, bx[nt], by[nt]);
        }
      }

      // Reduce across 4 K-groups into 2 buffers.
      // Rows: r 0-31, z 32-63, n_ih 64-95, n_hh 96-127.
      float* buf = (kg & 1) ? red1 : red0;
      if (kg < 2) {
#pragma unroll
        for (int m = 0; m < 3; m++) {
          int mtp = mh * 3 + m;
          int base = (mtp < 4) ? mtp * 16 : 64 + (mtp - 4) * 16;
          int row = base + g4;
#pragma unroll
          for (int nt = 0; nt < 8; nt++) {
            int col = nt * 8 + (l4 << 1);
            *(float2*)(buf + row * RED_LD + col) =
                make_float2(acc[m][nt][0], acc[m][nt][1]);
            *(float2*)(buf + (row + 8) * RED_LD + col) =
                make_float2(acc[m][nt][2], acc[m][nt][3]);
          }
        }
      } else if (mh == 1) {
#pragma unroll
        for (int m = 1; m < 3; m++) {
          int base = 96 + (3 + m - 4) * 16;
          int row = base + g4;
#pragma unroll
          for (int nt = 0; nt < 8; nt++) {
            int col = nt * 8 + (l4 << 1);
            *(float2*)(buf + row * RED_LD + col) =
                make_float2(acc[m][nt][0], acc[m][nt][1]);
            *(float2*)(buf + (row + 8) * RED_LD + col) =
                make_float2(acc[m][nt][2], acc[m][nt][3]);
          }
        }
      }
      __syncthreads();
      if (kg >= 2) {
#pragma unroll
        for (int m = 0; m < 3; m++) {
          int mtp = mh * 3 + m;
          if (mtp < 4) {
            int row = mtp * 16 + g4;
#pragma unroll
            for (int nt = 0; nt < 8; nt++) {
              int col = nt * 8 + (l4 << 1);
              float2* p0 = (float2*)(buf + row * RED_LD + col);
              float2* p1 = (float2*)(buf + (row + 8) * RED_LD + col);
              float2 v0 = *p0, v1 = *p1;
              v0.x += acc[m][nt][0]; v0.y += acc[m][nt][1];
              v1.x += acc[m][nt][2]; v1.y += acc[m][nt][3];
              *p0 = v0; *p1 = v1;
            }
          }
        }
      }
      __syncthreads();

      // Gate epilogue + publish
      unsigned short* hout = (unsigned short*)(g_hp16 +
          (size_t)((s & 1) * kL + layer) * 32768);
#pragma unroll
      for (int k = 0; k < 8; k++) {
        int e = tid + k * WTH;
        int jj = e >> 6, b = e & 63;
        float vr   = red0[jj * RED_LD + b]        + red1[jj * RED_LD + b];
        float vz   = red0[(32 + jj) * RED_LD + b] + red1[(32 + jj) * RED_LD + b];
        float vnih = red0[(64 + jj) * RED_LD + b] + red1[(64 + jj) * RED_LD + b];
        float vnhh = red0[(96 + jj) * RED_LD + b] + red1[(96 + jj) * RED_LD + b];
        float r = sigmoidf_(vr + sbias[jj] + sbias[96 + jj]);
        float z = sigmoidf_(vz + sbias[32 + jj] + sbias[128 + jj]);
        float n = tanhf(vnih + sbias[64 + jj] + r * (vnhh + sbias[160 + jj]));
        float h = (1.0f - z) * n + z * hp[k];
        hp[k] = h;
        int jg = j0 + jj;
        hout[hp_half_index(jg, b)] = __half_as_ushort(__float2half_rn(h));
        if (t == kT - 1)
          out[(size_t)layer * kB * kH + (size_t)b * kH + jg] = h;
      }
    }
    grid_barrier((unsigned)s);
  }
}

// ---------------------------------------------------------------------------
// Launch
// ---------------------------------------------------------------------------
extern "C" void kernel_launch(void* const* d_in, const int* in_sizes, int n_in,
                              void* d_out, int out_size) {
  (void)in_sizes; (void)n_in; (void)out_size;
  const float* x   = (const float*)d_in[0];
  const float* h0  = (const float*)d_in[1];
  const float* wih = (const float*)d_in[2];
  const float* whh = (const float*)d_in[3];
  const float* bih = (const float*)d_in[4];
  const float* bhh = (const float*)d_in[5];
  float* out = (float*)d_out;

  cudaFuncSetAttribute(wave_kernel, cudaFuncAttributeMaxDynamicSharedMemorySize,
                       WV_SMEM);

  // Idempotent packing passes
  {
    size_t nw = WP_U32;
    pack_w_kernel<<<(unsigned)((nw + 255) / 256), 256>>>(wih, whh);
    size_t nx = (size_t)kT * kB * 512;
    pack_x_kernel<<<(unsigned)((nx + 255) / 256), 256>>>(x);
    pack_h0_kernel<<<(kL * 32768) / 256, 256>>>(h0);
    reset_bar_kernel<<<1, 1>>>();
  }

  wave_kernel<<<WNCTA, WTH, WV_SMEM>>>(h0, bih, bhh, out);
}

// round 16
// speedup vs baseline: 1.0877x; 1.0877x over previous
#include <cuda_runtime.h>
#include <cuda_fp16.h>
#include <cstdint>
#include <cstddef>

// Problem constants
#define kT 512
#define kB 64
#define kH 1024
#define kG 3072
#define kL 4

// Wavefront config: 128 CTAs = 4 layers x 32 slices (32 hidden units each).
// 8 warps = 4 K-groups (K=512 each of K=2048) x 2 M-halves (48 gate rows).
#define WNCTA 128
#define WTH 256
#define NSTEP (kT + kL - 1)          /* 515 */
#define RED_LD 66
#define RED_ROWS 128                  /* r(32) z(32) n_ih(32) n_hh(32) */
#define NS 12                         /* kbl slices staged in SMEM per warp */
#define RED_FLOATS (2 * RED_ROWS * RED_LD + 192)      /* 17088 */
#define WV_SMEM ((RED_FLOATS * 4) + (NS * 12288))     /* 68352+147456=215808 */

// Packed weights: [cta][kg][mh][m(3)][kbl(32)][lane(32)] x uint4 (fp16 frags)
#define WP_U32 ((size_t)WNCTA * 4 * 2 * 3 * 32 * 32 * 4)   /* 12.58M u32 = 50MB */

// ---------------------------------------------------------------------------
// Scratch
// ---------------------------------------------------------------------------
__device__ unsigned g_wp_u32[WP_U32];
__device__ unsigned g_x16[(size_t)kT * 32768];   // packed fp16 x, per t: 32768 u32
__device__ unsigned g_hp16[2 * kL * 32768];      // h ping-pong per (parity, layer)
__device__ unsigned g_h016[kL * 32768];          // packed fp16 h0 per layer
__device__ unsigned g_count;
__device__ unsigned g_release;

__global__ void reset_bar_kernel() { g_count = 0u; g_release = 0u; }

// Proven threadfence grid barrier (128 CTAs).
__device__ __forceinline__ void grid_barrier(unsigned idx) {
  __syncthreads();
  if (threadIdx.x == 0) {
    __threadfence();
    unsigned old = atomicAdd(&g_count, 1u);
    if (old == (unsigned)WNCTA * (idx + 1u) - 1u) {
      __threadfence();
      asm volatile("st.release.gpu.global.u32 [%0], %1;"
                   :: "l"(&g_release), "r"(idx + 1u) : "memory");
    } else {
      while (*(volatile unsigned*)&g_release < idx + 1u) { }
    }
    __threadfence();
  }
  __syncthreads();
}

__device__ __forceinline__ float sigmoidf_(float x) {
  return 1.0f / (1.0f + expf(-x));
}

// R12/R13 packed h layout: per (k16-block kb, batch b): 8 half2 units ordered
// [p0,p4,p1,p5,p2,p6,p3,p7]; lane l4 reads B fragment (b0,b1) as one uint2.
__device__ __forceinline__ int hT16_half_index(int j, int b) {
  int kb = j >> 4;
  int p = (j & 15) >> 1;
  int slot = ((p & 3) << 1) + (p >> 2);
  return (((kb << 6) + b) * 8 + slot) * 2 + (j & 1);
}
__device__ __forceinline__ int hT16_u32_index(int j, int b) {   // even j
  int kb = j >> 4;
  int p = (j & 15) >> 1;
  int slot = ((p & 3) << 1) + (p >> 2);
  return ((kb << 6) + b) * 8 + slot;
}

#define MMA_F16(d, a, b0, b1)                                               \
  asm volatile(                                                             \
      "mma.sync.aligned.m16n8k16.row.col.f32.f16.f16.f32 "                  \
      "{%0,%1,%2,%3}, {%4,%5,%6,%7}, {%8,%9}, {%0,%1,%2,%3};"               \
      : "+f"(d[0]), "+f"(d[1]), "+f"(d[2]), "+f"(d[3])                      \
      : "r"(a.x), "r"(a.y), "r"(a.z), "r"(a.w), "r"(b0), "r"(b1))

// ---------------------------------------------------------------------------
// Packing kernels (idempotent, run every launch)
// ---------------------------------------------------------------------------
__global__ void pack_w_kernel(const float* __restrict__ wih,
                              const float* __restrict__ whh) {
  size_t i = (size_t)blockIdx.x * blockDim.x + threadIdx.x;
  if (i >= WP_U32) return;
  int e = (int)(i & 3);
  int lane = (int)((i >> 2) & 31);
  int kbl = (int)((i >> 7) & 31);
  int rem = (int)(i >> 12);
  int m = rem % 3; rem /= 3;
  int mh = rem & 1;
  int kg = (rem >> 1) & 3;
  int cta = rem >> 3;
  int layer = cta >> 5, slice = cta & 31;
  int mtp = mh * 3 + m;
  int gate = mtp >> 1;
  int rr = ((mtp & 1) << 4) + (lane >> 2) + ((e & 1) << 3);
  int k = (kg * 32 + kbl) * 16 + ((lane & 3) << 1) + ((e >> 1) << 3);
  int row = gate * kH + slice * 32 + rr;
  const float* W = (k < kH) ? (wih + (size_t)layer * kG * kH)
                            : (whh + (size_t)layer * kG * kH);
  int kk = k & (kH - 1);
  __half2 h2 = __floats2half2_rn(W[(size_t)row * kH + kk],
                                 W[(size_t)row * kH + kk + 1]);
  g_wp_u32[i] = *(unsigned*)&h2;
}

__global__ void pack_x_kernel(const float* __restrict__ x) {
  size_t i = (size_t)blockIdx.x * blockDim.x + threadIdx.x;  // < kT*kB*512
  int t = (int)(i >> 15);
  int r = (int)(i & 32767);
  int b = r >> 9;
  int j = (r & 511) << 1;
  const float* src = x + (size_t)t * kB * kH + (size_t)b * kH + j;
  __half2 h2 = __floats2half2_rn(src[0], src[1]);
  g_x16[(size_t)t * 32768 + hT16_u32_index(j, b)] = *(unsigned*)&h2;
}

__global__ void pack_h0_kernel(const float* __restrict__ h0) {
  int i = blockIdx.x * blockDim.x + threadIdx.x;   // < kL*32768
  int layer = i >> 15;
  int r = i & 32767;
  int b = r >> 9;
  int j = (r & 511) << 1;
  const float* src = h0 + (size_t)layer * kB * kH + (size_t)b * kH + j;
  __half2 h2 = __floats2half2_rn(src[0], src[1]);
  g_h016[layer * 32768 + hT16_u32_index(j, b)] = *(unsigned*)&h2;
}

// ---------------------------------------------------------------------------
// Wavefront kernel (R13 structure): 128 CTAs, 515 steps.
// NEW: first NS kbl-slices of each warp's weights live in SMEM (persistent,
// copied once) -> weight L2 traffic cut 37.5%. Streamed remainder via __ldcg
// (read-once; keeps L1 for the h twin-warp reuse). h path identical to R13.
// ---------------------------------------------------------------------------
__global__ void __launch_bounds__(WTH, 1) wave_kernel(
    const float* __restrict__ h0f,
    const float* __restrict__ bih,
    const float* __restrict__ bhh,
    float* __restrict__ out) {
  extern __shared__ float sm[];
  float* red0 = sm;                          // [128][RED_LD]
  float* red1 = sm + RED_ROWS * RED_LD;
  float* sbias = sm + 2 * RED_ROWS * RED_LD; // [6][32]
  uint4* sW = (uint4*)(sm + RED_FLOATS);     // [8 warps][3][NS][32] frags
  const int tid = threadIdx.x;
  const int lane = tid & 31;
  const int wid = tid >> 5;
  const int layer = blockIdx.x >> 5;
  const int slice = blockIdx.x & 31;
  const int j0 = slice * 32;

  // Stage biases: [bi_r, bi_z, bi_n, bh_r, bh_z, bh_n][jj]
  for (int i = tid; i < 192; i += WTH) {
    int g = i >> 5, jj = i & 31;
    sbias[i] = ((g < 3) ? bih : bhh)[(size_t)layer * kG + (g % 3) * kH + j0 + jj];
  }

  // Register-resident h_prev: thread owns 8 (jj, b) outputs.
  float hp[8];
#pragma unroll
  for (int k = 0; k < 8; k++) {
    int e = tid + k * WTH;
    int jj = e >> 6, b = e & 63;
    hp[k] = h0f[(size_t)layer * kB * kH + (size_t)b * kH + j0 + jj];
  }

  const int kg = wid >> 1;          // K group: 0,1 = ih half; 2,3 = hh half
  const int mh = wid & 1;           // M half (3 of 6 m-tiles)
  const int g4 = lane >> 2;
  const int l4 = lane & 3;
  const uint4* wpw = (const uint4*)g_wp_u32 +
      ((((size_t)blockIdx.x * 4 + kg) * 2 + mh) * 3 * 32 * 32);
  uint4* sWw = sW + (size_t)wid * 3 * NS * 32;

  // One-time weight staging: each warp copies its first NS kbl slices.
#pragma unroll
  for (int m = 0; m < 3; m++)
    for (int kbl = 0; kbl < NS; kbl++)
      sWw[(m * NS + kbl) * 32 + lane] = wpw[(m * 32 + kbl) * 32 + lane];
  __syncthreads();

  for (int s = 0; s < NSTEP; s++) {
    int t = s - layer;
    if (t >= 0 && t < kT) {
      // B-operand source for this warp's K half (R13 form, L1-cacheable)
      const uint2* bsrc;
      if (kg < 2) {
        bsrc = (layer == 0)
            ? (const uint2*)(g_x16 + (size_t)t * 32768)
            : (const uint2*)(g_hp16 + (size_t)(((s - 1) & 1) * kL + (layer - 1)) * 32768);
      } else {
        bsrc = (t == 0)
            ? (const uint2*)(g_h016 + (size_t)layer * 32768)
            : (const uint2*)(g_hp16 + (size_t)(((s - 1) & 1) * kL + layer) * 32768);
      }

      float acc[3][8][4];
#pragma unroll
      for (int m = 0; m < 3; m++)
#pragma unroll
        for (int nt = 0; nt < 8; nt++)
#pragma unroll
          for (int e = 0; e < 4; e++) acc[m][nt][e] = 0.0f;

      // --- kbl 0..NS-1: weights from SMEM (conflict-free LDS.128) ---
#pragma unroll 4
      for (int kbl = 0; kbl < NS; kbl++) {
        int kb_src = (kg * 32 + kbl) & 63;
        uint4 a0 = sWw[(0 * NS + kbl) * 32 + lane];
        uint4 a1 = sWw[(1 * NS + kbl) * 32 + lane];
        uint4 a2 = sWw[(2 * NS + kbl) * 32 + lane];
        uint32_t bx[8], by[8];
#pragma unroll
        for (int nt = 0; nt < 8; nt++) {
          uint2 p = bsrc[((size_t)(kb_src * 64 + nt * 8 + g4)) * 4 + l4];
          bx[nt] = p.x; by[nt] = p.y;
        }
#pragma unroll
        for (int nt = 0; nt < 8; nt++) {
          MMA_F16(acc[0][nt], a0, bx[nt], by[nt]);
          MMA_F16(acc[1][nt], a1, bx[nt], by[nt]);
          MMA_F16(acc[2][nt], a2, bx[nt], by[nt]);
        }
      }
      // --- kbl NS..31: weights streamed from L2 (__ldcg, read-once) ---
#pragma unroll 4
      for (int kbl = NS; kbl < 32; kbl++) {
        int kb_src = (kg * 32 + kbl) & 63;
        uint4 a0 = __ldcg(&wpw[(0 * 32 + kbl) * 32 + lane]);
        uint4 a1 = __ldcg(&wpw[(1 * 32 + kbl) * 32 + lane]);
        uint4 a2 = __ldcg(&wpw[(2 * 32 + kbl) * 32 + lane]);
        uint32_t bx[8], by[8];
#pragma unroll
        for (int nt = 0; nt < 8; nt++) {
          uint2 p = bsrc[((size_t)(kb_src * 64 + nt * 8 + g4)) * 4 + l4];
          bx[nt] = p.x; by[nt] = p.y;
        }
#pragma unroll
        for (int nt = 0; nt < 8; nt++) {
          MMA_F16(acc[0][nt], a0, bx[nt], by[nt]);
          MMA_F16(acc[1][nt], a1, bx[nt], by[nt]);
          MMA_F16(acc[2][nt], a2, bx[nt], by[nt]);
        }
      }

      // Reduce across 4 K-groups into 2 buffers.
      // Rows: r 0-31, z 32-63, n_ih 64-95, n_hh 96-127.
      float* buf = (kg & 1) ? red1 : red0;
      if (kg < 2) {
#pragma unroll
        for (int m = 0; m < 3; m++) {
          int mtp = mh * 3 + m;
          int base = (mtp < 4) ? mtp * 16 : 64 + (mtp - 4) * 16;
          int row = base + g4;
#pragma unroll
          for (int nt = 0; nt < 8; nt++) {
            int col = nt * 8 + (l4 << 1);
            *(float2*)(buf + row * RED_LD + col) =
                make_float2(acc[m][nt][0], acc[m][nt][1]);
            *(float2*)(buf + (row + 8) * RED_LD + col) =
                make_float2(acc[m][nt][2], acc[m][nt][3]);
          }
        }
      } else if (mh == 1) {
#pragma unroll
        for (int m = 1; m < 3; m++) {
          int base = 96 + (3 + m - 4) * 16;
          int row = base + g4;
#pragma unroll
          for (int nt = 0; nt < 8; nt++) {
            int col = nt * 8 + (l4 << 1);
            *(float2*)(buf + row * RED_LD + col) =
                make_float2(acc[m][nt][0], acc[m][nt][1]);
            *(float2*)(buf + (row + 8) * RED_LD + col) =
                make_float2(acc[m][nt][2], acc[m][nt][3]);
          }
        }
      }
      __syncthreads();
      if (kg >= 2) {
#pragma unroll
        for (int m = 0; m < 3; m++) {
          int mtp = mh * 3 + m;
          if (mtp < 4) {
            int row = mtp * 16 + g4;
#pragma unroll
            for (int nt = 0; nt < 8; nt++) {
              int col = nt * 8 + (l4 << 1);
              float2* p0 = (float2*)(buf + row * RED_LD + col);
              float2* p1 = (float2*)(buf + (row + 8) * RED_LD + col);
              float2 v0 = *p0, v1 = *p1;
              v0.x += acc[m][nt][0]; v0.y += acc[m][nt][1];
              v1.x += acc[m][nt][2]; v1.y += acc[m][nt][3];
              *p0 = v0; *p1 = v1;
            }
          }
        }
      }
      __syncthreads();

      // Gate epilogue + publish
      unsigned short* hout = (unsigned short*)(g_hp16 +
          (size_t)((s & 1) * kL + layer) * 32768);
#pragma unroll
      for (int k = 0; k < 8; k++) {
        int e = tid + k * WTH;
        int jj = e >> 6, b = e & 63;
        float vr   = red0[jj * RED_LD + b]        + red1[jj * RED_LD + b];
        float vz   = red0[(32 + jj) * RED_LD + b] + red1[(32 + jj) * RED_LD + b];
        float vnih = red0[(64 + jj) * RED_LD + b] + red1[(64 + jj) * RED_LD + b];
        float vnhh = red0[(96 + jj) * RED_LD + b] + red1[(96 + jj) * RED_LD + b];
        float r = sigmoidf_(vr + sbias[jj] + sbias[96 + jj]);
        float z = sigmoidf_(vz + sbias[32 + jj] + sbias[128 + jj]);
        float n = tanhf(vnih + sbias[64 + jj] + r * (vnhh + sbias[160 + jj]));
        float h = (1.0f - z) * n + z * hp[k];
        hp[k] = h;
        int jg = j0 + jj;
        hout[hT16_half_index(jg, b)] = __half_as_ushort(__float2half_rn(h));
        if (t == kT - 1)
          out[(size_t)layer * kB * kH + (size_t)b * kH + jg] = h;
      }
    }
    grid_barrier((unsigned)s);
  }
}

// ---------------------------------------------------------------------------
// Launch
// ---------------------------------------------------------------------------
extern "C" void kernel_launch(void* const* d_in, const int* in_sizes, int n_in,
                              void* d_out, int out_size) {
  (void)in_sizes; (void)n_in; (void)out_size;
  const float* x   = (const float*)d_in[0];
  const float* h0  = (const float*)d_in[1];
  const float* wih = (const float*)d_in[2];
  const float* whh = (const float*)d_in[3];
  const float* bih = (const float*)d_in[4];
  const float* bhh = (const float*)d_in[5];
  float* out = (float*)d_out;

  cudaFuncSetAttribute(wave_kernel, cudaFuncAttributeMaxDynamicSharedMemorySize,
                       WV_SMEM);

  // Idempotent packing passes
  {
    size_t nw = WP_U32;
    pack_w_kernel<<<(unsigned)((nw + 255) / 256), 256>>>(wih, whh);
    size_t nx = (size_t)kT * kB * 512;
    pack_x_kernel<<<(unsigned)((nx + 255) / 256), 256>>>(x);
    pack_h0_kernel<<<(kL * 32768) / 256, 256>>>(h0);
    reset_bar_kernel<<<1, 1>>>();
  }

  wave_kernel<<<WNCTA, WTH, WV_SMEM>>>(h0, bih, bhh, out);
}

// round 17
// speedup vs baseline: 1.1054x; 1.0163x over previous
#include <cuda_runtime.h>
#include <cuda_fp16.h>
#include <cstdint>
#include <cstddef>

// Problem constants
#define kT 512
#define kB 64
#define kH 1024
#define kG 3072
#define kL 4

// Wavefront config: 128 CTAs = 4 layers x 32 slices (32 hidden units each).
// 8 warps = 4 K-groups (K=512 each of K=2048) x 2 M-halves (48 gate rows).
#define WNCTA 128
#define WTH 256
#define RED_LD 66
#define RED_ROWS 128                  /* r(32) z(32) n_ih(32) n_hh(32) */
#define NS 12                         /* kbl slices staged in SMEM per warp */
#define RED_FLOATS (2 * RED_ROWS * RED_LD + 192)      /* 17088 */
#define WV_SMEM ((RED_FLOATS * 4) + (NS * 12288))     /* 215808 B */
#define RING 4                        /* h ring depth (parity (t+layer)&3) */

// Packed weights: [cta][kg][mh][m(3)][kbl(32)][lane(32)] x uint4 (fp16 frags)
#define WP_U32 ((size_t)WNCTA * 4 * 2 * 3 * 32 * 32 * 4)   /* 12.58M u32 = 50MB */

// ---------------------------------------------------------------------------
// Scratch
// ---------------------------------------------------------------------------
__device__ unsigned g_wp_u32[WP_U32];
__device__ unsigned g_x16[(size_t)kT * 32768];    // packed fp16 x, per t
__device__ unsigned g_hp16[RING * kL * 32768];    // h ring per (parity, layer)
__device__ unsigned g_h016[kL * 32768];           // packed fp16 h0 per layer
__device__ unsigned g_done[kL * 32 * 8];          // per-(layer,slice) step flags, 32B pad

__global__ void reset_flags_kernel() {
  int i = blockIdx.x * blockDim.x + threadIdx.x;
  if (i < kL * 32 * 8) g_done[i] = 0u;
}

__device__ __forceinline__ float sigmoidf_(float x) {
  return 1.0f / (1.0f + expf(-x));
}

// R12/R13 packed h layout: per (k16-block kb, batch b): 8 half2 units ordered
// [p0,p4,p1,p5,p2,p6,p3,p7]; lane l4 reads B fragment (b0,b1) as one uint2.
__device__ __forceinline__ int hT16_half_index(int j, int b) {
  int kb = j >> 4;
  int p = (j & 15) >> 1;
  int slot = ((p & 3) << 1) + (p >> 2);
  return (((kb << 6) + b) * 8 + slot) * 2 + (j & 1);
}
__device__ __forceinline__ int hT16_u32_index(int j, int b) {   // even j
  int kb = j >> 4;
  int p = (j & 15) >> 1;
  int slot = ((p & 3) << 1) + (p >> 2);
  return ((kb << 6) + b) * 8 + slot;
}

#define MMA_F16(d, a, b0, b1)                                               \
  asm volatile(                                                             \
      "mma.sync.aligned.m16n8k16.row.col.f32.f16.f16.f32 "                  \
      "{%0,%1,%2,%3}, {%4,%5,%6,%7}, {%8,%9}, {%0,%1,%2,%3};"               \
      : "+f"(d[0]), "+f"(d[1]), "+f"(d[2]), "+f"(d[3])                      \
      : "r"(a.x), "r"(a.y), "r"(a.z), "r"(a.w), "r"(b0), "r"(b1))

__device__ __forceinline__ unsigned flag_load_acq(const unsigned* p) {
  unsigned v;
  asm volatile("ld.acquire.gpu.global.u32 %0, [%1];" : "=r"(v) : "l"(p) : "memory");
  return v;
}

// ---------------------------------------------------------------------------
// Packing kernels (idempotent, run every launch)
// ---------------------------------------------------------------------------
__global__ void pack_w_kernel(const float* __restrict__ wih,
                              const float* __restrict__ whh) {
  size_t i = (size_t)blockIdx.x * blockDim.x + threadIdx.x;
  if (i >= WP_U32) return;
  int e = (int)(i & 3);
  int lane = (int)((i >> 2) & 31);
  int kbl = (int)((i >> 7) & 31);
  int rem = (int)(i >> 12);
  int m = rem % 3; rem /= 3;
  int mh = rem & 1;
  int kg = (rem >> 1) & 3;
  int cta = rem >> 3;
  int layer = cta >> 5, slice = cta & 31;
  int mtp = mh * 3 + m;
  int gate = mtp >> 1;
  int rr = ((mtp & 1) << 4) + (lane >> 2) + ((e & 1) << 3);
  int k = (kg * 32 + kbl) * 16 + ((lane & 3) << 1) + ((e >> 1) << 3);
  int row = gate * kH + slice * 32 + rr;
  const float* W = (k < kH) ? (wih + (size_t)layer * kG * kH)
                            : (whh + (size_t)layer * kG * kH);
  int kk = k & (kH - 1);
  __half2 h2 = __floats2half2_rn(W[(size_t)row * kH + kk],
                                 W[(size_t)row * kH + kk + 1]);
  g_wp_u32[i] = *(unsigned*)&h2;
}

__global__ void pack_x_kernel(const float* __restrict__ x) {
  size_t i = (size_t)blockIdx.x * blockDim.x + threadIdx.x;  // < kT*kB*512
  int t = (int)(i >> 15);
  int r = (int)(i & 32767);
  int b = r >> 9;
  int j = (r & 511) << 1;
  const float* src = x + (size_t)t * kB * kH + (size_t)b * kH + j;
  __half2 h2 = __floats2half2_rn(src[0], src[1]);
  g_x16[(size_t)t * 32768 + hT16_u32_index(j, b)] = *(unsigned*)&h2;
}

__global__ void pack_h0_kernel(const float* __restrict__ h0) {
  int i = blockIdx.x * blockDim.x + threadIdx.x;   // < kL*32768
  int layer = i >> 15;
  int r = i & 32767;
  int b = r >> 9;
  int j = (r & 511) << 1;
  const float* src = h0 + (size_t)layer * kB * kH + (size_t)b * kH + j;
  __half2 h2 = __floats2half2_rn(src[0], src[1]);
  g_h016[layer * 32768 + hT16_u32_index(j, b)] = *(unsigned*)&h2;
}

// ---------------------------------------------------------------------------
// Self-timed wavefront: 128 CTAs loop over their own 512 timesteps, gated
// only by true dependencies via per-(layer,slice) release/acquire step flags.
// Compute path bit-identical to R15 (SMEM-staged + __ldcg-streamed weights).
// ---------------------------------------------------------------------------
__global__ void __launch_bounds__(WTH, 1) wave_kernel(
    const float* __restrict__ h0f,
    const float* __restrict__ bih,
    const float* __restrict__ bhh,
    float* __restrict__ out) {
  extern __shared__ float sm[];
  float* red0 = sm;                          // [128][RED_LD]
  float* red1 = sm + RED_ROWS * RED_LD;
  float* sbias = sm + 2 * RED_ROWS * RED_LD; // [6][32]
  uint4* sW = (uint4*)(sm + RED_FLOATS);     // [8 warps][3][NS][32] frags
  const int tid = threadIdx.x;
  const int lane = tid & 31;
  const int wid = tid >> 5;
  const int layer = blockIdx.x >> 5;
  const int slice = blockIdx.x & 31;
  const int j0 = slice * 32;

  // Stage biases: [bi_r, bi_z, bi_n, bh_r, bh_z, bh_n][jj]
  for (int i = tid; i < 192; i += WTH) {
    int g = i >> 5, jj = i & 31;
    sbias[i] = ((g < 3) ? bih : bhh)[(size_t)layer * kG + (g % 3) * kH + j0 + jj];
  }

  // Register-resident h_prev: thread owns 8 (jj, b) outputs.
  float hp[8];
#pragma unroll
  for (int k = 0; k < 8; k++) {
    int e = tid + k * WTH;
    int jj = e >> 6, b = e & 63;
    hp[k] = h0f[(size_t)layer * kB * kH + (size_t)b * kH + j0 + jj];
  }

  const int kg = wid >> 1;          // K group: 0,1 = ih half; 2,3 = hh half
  const int mh = wid & 1;           // M half (3 of 6 m-tiles)
  const int g4 = lane >> 2;
  const int l4 = lane & 3;
  const uint4* wpw = (const uint4*)g_wp_u32 +
      ((((size_t)blockIdx.x * 4 + kg) * 2 + mh) * 3 * 32 * 32);
  uint4* sWw = sW + (size_t)wid * 3 * NS * 32;

  // One-time weight staging: each warp copies its first NS kbl slices.
#pragma unroll
  for (int m = 0; m < 3; m++)
    for (int kbl = 0; kbl < NS; kbl++)
      sWw[(m * NS + kbl) * 32 + lane] = wpw[(m * 32 + kbl) * 32 + lane];
  __syncthreads();

  for (int t = 0; t < kT; t++) {
    const int s = t + layer;

    // ---- Dependency waits (parallel, one flag per thread) ----
    // threads 0-31:  own-layer siblings finished t-1  (need flag >= t)
    // threads 32-63: layer-1 finished t               (need flag >= t+1)
    // threads 64-95: layer+1 finished t-4 (ring back-pressure, >= t-3)
    if (t > 0 && tid < 32) {
      const unsigned* f = &g_done[(layer * 32 + tid) * 8];
      while (flag_load_acq(f) < (unsigned)t) { }
    }
    if (layer > 0 && tid >= 32 && tid < 64) {
      const unsigned* f = &g_done[((layer - 1) * 32 + (tid - 32)) * 8];
      while (flag_load_acq(f) < (unsigned)(t + 1)) { }
    }
    if (layer < kL - 1 && t >= RING && tid >= 64 && tid < 96) {
      const unsigned* f = &g_done[((layer + 1) * 32 + (tid - 64)) * 8];
      while (flag_load_acq(f) < (unsigned)(t - RING + 1)) { }
    }
    __syncthreads();

    // ---- B-operand source for this warp's K half ----
    const uint2* bsrc;
    if (kg < 2) {
      bsrc = (layer == 0)
          ? (const uint2*)(g_x16 + (size_t)t * 32768)
          : (const uint2*)(g_hp16 + (size_t)((((s - 1) & (RING - 1)) * kL) + (layer - 1)) * 32768);
    } else {
      bsrc = (t == 0)
          ? (const uint2*)(g_h016 + (size_t)layer * 32768)
          : (const uint2*)(g_hp16 + (size_t)((((s - 1) & (RING - 1)) * kL) + layer) * 32768);
    }

    float acc[3][8][4];
#pragma unroll
    for (int m = 0; m < 3; m++)
#pragma unroll
      for (int nt = 0; nt < 8; nt++)
#pragma unroll
        for (int e = 0; e < 4; e++) acc[m][nt][e] = 0.0f;

    // --- kbl 0..NS-1: weights from SMEM (conflict-free LDS.128) ---
#pragma unroll 4
    for (int kbl = 0; kbl < NS; kbl++) {
      int kb_src = (kg * 32 + kbl) & 63;
      uint4 a0 = sWw[(0 * NS + kbl) * 32 + lane];
      uint4 a1 = sWw[(1 * NS + kbl) * 32 + lane];
      uint4 a2 = sWw[(2 * NS + kbl) * 32 + lane];
      uint32_t bx[8], by[8];
#pragma unroll
      for (int nt = 0; nt < 8; nt++) {
        uint2 p = bsrc[((size_t)(kb_src * 64 + nt * 8 + g4)) * 4 + l4];
        bx[nt] = p.x; by[nt] = p.y;
      }
#pragma unroll
      for (int nt = 0; nt < 8; nt++) {
        MMA_F16(acc[0][nt], a0, bx[nt], by[nt]);
        MMA_F16(acc[1][nt], a1, bx[nt], by[nt]);
        MMA_F16(acc[2][nt], a2, bx[nt], by[nt]);
      }
    }
    // --- kbl NS..31: weights streamed from L2 (__ldcg, read-once) ---
#pragma unroll 4
    for (int kbl = NS; kbl < 32; kbl++) {
      int kb_src = (kg * 32 + kbl) & 63;
      uint4 a0 = __ldcg(&wpw[(0 * 32 + kbl) * 32 + lane]);
      uint4 a1 = __ldcg(&wpw[(1 * 32 + kbl) * 32 + lane]);
      uint4 a2 = __ldcg(&wpw[(2 * 32 + kbl) * 32 + lane]);
      uint32_t bx[8], by[8];
#pragma unroll
      for (int nt = 0; nt < 8; nt++) {
        uint2 p = bsrc[((size_t)(kb_src * 64 + nt * 8 + g4)) * 4 + l4];
        bx[nt] = p.x; by[nt] = p.y;
      }
#pragma unroll
      for (int nt = 0; nt < 8; nt++) {
        MMA_F16(acc[0][nt], a0, bx[nt], by[nt]);
        MMA_F16(acc[1][nt], a1, bx[nt], by[nt]);
        MMA_F16(acc[2][nt], a2, bx[nt], by[nt]);
      }
    }

    // Reduce across 4 K-groups into 2 buffers.
    // Rows: r 0-31, z 32-63, n_ih 64-95, n_hh 96-127.
    float* buf = (kg & 1) ? red1 : red0;
    if (kg < 2) {
#pragma unroll
      for (int m = 0; m < 3; m++) {
        int mtp = mh * 3 + m;
        int base = (mtp < 4) ? mtp * 16 : 64 + (mtp - 4) * 16;
        int row = base + g4;
#pragma unroll
        for (int nt = 0; nt < 8; nt++) {
          int col = nt * 8 + (l4 << 1);
          *(float2*)(buf + row * RED_LD + col) =
              make_float2(acc[m][nt][0], acc[m][nt][1]);
          *(float2*)(buf + (row + 8) * RED_LD + col) =
              make_float2(acc[m][nt][2], acc[m][nt][3]);
        }
      }
    } else if (mh == 1) {
#pragma unroll
      for (int m = 1; m < 3; m++) {
        int base = 96 + (3 + m - 4) * 16;
        int row = base + g4;
#pragma unroll
        for (int nt = 0; nt < 8; nt++) {
          int col = nt * 8 + (l4 << 1);
          *(float2*)(buf + row * RED_LD + col) =
              make_float2(acc[m][nt][0], acc[m][nt][1]);
          *(float2*)(buf + (row + 8) * RED_LD + col) =
              make_float2(acc[m][nt][2], acc[m][nt][3]);
        }
      }
    }
    __syncthreads();
    if (kg >= 2) {
#pragma unroll
      for (int m = 0; m < 3; m++) {
        int mtp = mh * 3 + m;
        if (mtp < 4) {
          int row = mtp * 16 + g4;
#pragma unroll
          for (int nt = 0; nt < 8; nt++) {
            int col = nt * 8 + (l4 << 1);
            float2* p0 = (float2*)(buf + row * RED_LD + col);
            float2* p1 = (float2*)(buf + (row + 8) * RED_LD + col);
            float2 v0 = *p0, v1 = *p1;
            v0.x += acc[m][nt][0]; v0.y += acc[m][nt][1];
            v1.x += acc[m][nt][2]; v1.y += acc[m][nt][3];
            *p0 = v0; *p1 = v1;
          }
        }
      }
    }
    __syncthreads();

    // Gate epilogue + publish into ring slot (s & 3)
    unsigned short* hout = (unsigned short*)(g_hp16 +
        (size_t)(((s & (RING - 1)) * kL) + layer) * 32768);
#pragma unroll
    for (int k = 0; k < 8; k++) {
      int e = tid + k * WTH;
      int jj = e >> 6, b = e & 63;
      float vr   = red0[jj * RED_LD + b]        + red1[jj * RED_LD + b];
      float vz   = red0[(32 + jj) * RED_LD + b] + red1[(32 + jj) * RED_LD + b];
      float vnih = red0[(64 + jj) * RED_LD + b] + red1[(64 + jj) * RED_LD + b];
      float vnhh = red0[(96 + jj) * RED_LD + b] + red1[(96 + jj) * RED_LD + b];
      float r = sigmoidf_(vr + sbias[jj] + sbias[96 + jj]);
      float z = sigmoidf_(vz + sbias[32 + jj] + sbias[128 + jj]);
      float n = tanhf(vnih + sbias[64 + jj] + r * (vnhh + sbias[160 + jj]));
      float h = (1.0f - z) * n + z * hp[k];
      hp[k] = h;
      int jg = j0 + jj;
      hout[hT16_half_index(jg, b)] = __half_as_ushort(__float2half_rn(h));
      if (t == kT - 1)
        out[(size_t)layer * kB * kH + (size_t)b * kH + jg] = h;
    }

    // Publish completion of step t: all warps' h stores happen-before the
    // release store (syncthreads -> st.release, proven pattern).
    __syncthreads();
    if (tid == 0) {
      asm volatile("st.release.gpu.global.u32 [%0], %1;"
                   :: "l"(&g_done[(layer * 32 + slice) * 8]),
                      "r"((unsigned)(t + 1)) : "memory");
    }
  }
}

// ---------------------------------------------------------------------------
// Launch
// ---------------------------------------------------------------------------
extern "C" void kernel_launch(void* const* d_in, const int* in_sizes, int n_in,
                              void* d_out, int out_size) {
  (void)in_sizes; (void)n_in; (void)out_size;
  const float* x   = (const float*)d_in[0];
  const float* h0  = (const float*)d_in[1];
  const float* wih = (const float*)d_in[2];
  const float* whh = (const float*)d_in[3];
  const float* bih = (const float*)d_in[4];
  const float* bhh = (const float*)d_in[5];
  float* out = (float*)d_out;

  cudaFuncSetAttribute(wave_kernel, cudaFuncAttributeMaxDynamicSharedMemorySize,
                       WV_SMEM);

  // Idempotent packing passes
  {
    size_t nw = WP_U32;
    pack_w_kernel<<<(unsigned)((nw + 255) / 256), 256>>>(wih, whh);
    size_t nx = (size_t)kT * kB * 512;
    pack_x_kernel<<<(unsigned)((nx + 255) / 256), 256>>>(x);
    pack_h0_kernel<<<(kL * 32768) / 256, 256>>>(h0);
    reset_flags_kernel<<<4, 256>>>();
  }

  wave_kernel<<<WNCTA, WTH, WV_SMEM>>>(h0, bih, bhh, out);
}